// round 14
// baseline (speedup 1.0000x reference)
#include <cuda_runtime.h>
#include <cuda_fp16.h>
#include <cstdint>

#define N_NODES  100000
#define N_SCAN   (N_NODES + 1)
#define ROWSP    100096          // padded to multiple of 128
#define HALF_R   50048           // = 391 * 128
#define N_EDGES  250000
#define N_GRAPHS 512
#define VOCAB    1000
#define EMBED    256
#define HIDDEN   512
#define HALF_H   256
#define OUT_DIM  128
#define BN_EPS   1e-5f
#define SCAN_NBLK ((N_SCAN + 1023) / 1024)   // 98
#define CS_ROWS  338

// ---------------- scratch (device globals; no allocation allowed) ----------
__device__ float  g_E   [(size_t)VOCAB * HIDDEN];
__device__ __half g_y   [(size_t)N_NODES * HIDDEN];   // fp16 activations (y1, then y2)
__device__ float  g_stats[4 * HIDDEN];
__device__ float  g_coefA[2 * HIDDEN];
__device__ float  g_coefB[2 * HIDDEN];
__device__ float  g_pooled[N_GRAPHS * HIDDEN];
__device__ float  g_cnt[N_GRAPHS];
__device__ float  g_z[N_GRAPHS * HALF_H];
// CSR of in-edges (rebuilt per call)
__device__ int g_deg[N_SCAN];
__device__ int g_off[N_SCAN];
__device__ int g_cur[N_NODES];
__device__ int g_bsum[SCAN_NBLK];
__device__ int g_csr[N_EDGES];
// fp16 GEMM operands; pad rows never written -> stay zero
__device__ __half g_A [(size_t)ROWSP * HIDDEN];
__device__ __half g_Wt[HIDDEN * HIDDEN];              // [N][K] K-major

// ---------------- PTX helpers ----------------------------------------------
__device__ __forceinline__ uint32_t smem_u32(const void* p) {
    uint32_t a;
    asm("{ .reg .u64 t; cvta.to.shared.u64 t, %1; cvt.u32.u64 %0, t; }" : "=r"(a) : "l"(p));
    return a;
}
__device__ __forceinline__ void cp_async16(uint32_t dst, const void* src) {
    asm volatile("cp.async.cg.shared.global [%0], [%1], 16;" :: "r"(dst), "l"(src));
}
#define CP_COMMIT()  asm volatile("cp.async.commit_group;" ::: "memory")
#define CP_WAIT(n)   asm volatile("cp.async.wait_group %0;" :: "n"(n) : "memory")

__device__ __forceinline__ void ldm4(uint32_t* r, uint32_t addr) {
    asm volatile("ldmatrix.sync.aligned.m8n8.x4.shared.b16 {%0,%1,%2,%3}, [%4];"
                 : "=r"(r[0]), "=r"(r[1]), "=r"(r[2]), "=r"(r[3]) : "r"(addr));
}
__device__ __forceinline__ void mma_fp16(float* c, const uint32_t* a, const uint32_t* b) {
    asm volatile(
        "mma.sync.aligned.m16n8k16.row.col.f32.f16.f16.f32 "
        "{%0,%1,%2,%3}, {%4,%5,%6,%7}, {%8,%9}, {%0,%1,%2,%3};"
        : "+f"(c[0]), "+f"(c[1]), "+f"(c[2]), "+f"(c[3])
        : "r"(a[0]), "r"(a[1]), "r"(a[2]), "r"(a[3]), "r"(b[0]), "r"(b[1]));
}
__device__ __forceinline__ uint32_t swz(int row, int q) {
    return (uint32_t)(row * 64 + ((q ^ ((row >> 1) & 3)) << 4));
}
// load 4 consecutive halves (8B) as float4; idx in 4-half units
__device__ __forceinline__ float4 ldh4(const __half* Y, size_t idx) {
    uint2 raw = __ldg((const uint2*)Y + idx);
    __half2 a = *reinterpret_cast<__half2*>(&raw.x);
    __half2 b = *reinterpret_cast<__half2*>(&raw.y);
    float2 fa = __half22float2(a), fb = __half22float2(b);
    return make_float4(fa.x, fa.y, fb.x, fb.y);
}
__device__ __forceinline__ void sth4(__half* Y, size_t idx, float4 v) {
    __half2 h0 = __floats2half2_rn(v.x, v.y);
    __half2 h1 = __floats2half2_rn(v.z, v.w);
    uint2 o;
    o.x = *reinterpret_cast<uint32_t*>(&h0);
    o.y = *reinterpret_cast<uint32_t*>(&h1);
    ((uint2*)Y)[idx] = o;
}

// ---------------- tiny GEMM: E' = emb @ W1 ----------------------------------
__global__ void k_gemm_emb(const float* __restrict__ emb, const float* __restrict__ W1,
                           float* __restrict__ E) {
    __shared__ float er[4][EMBED];
    int r0 = blockIdx.x * 4, t = threadIdx.x;
#pragma unroll
    for (int i = 0; i < 4; i++) er[i][t] = emb[(size_t)(r0 + i) * EMBED + t];
    __syncthreads();
    float acc[4][2] = {};
    for (int k = 0; k < EMBED; k++) {
        float w0 = __ldg(&W1[(size_t)k * HIDDEN + t]);
        float w1 = __ldg(&W1[(size_t)k * HIDDEN + t + 256]);
#pragma unroll
        for (int i = 0; i < 4; i++) {
            acc[i][0] = fmaf(er[i][k], w0, acc[i][0]);
            acc[i][1] = fmaf(er[i][k], w1, acc[i][1]);
        }
    }
#pragma unroll
    for (int i = 0; i < 4; i++) {
        E[(size_t)(r0 + i) * HIDDEN + t]       = acc[i][0];
        E[(size_t)(r0 + i) * HIDDEN + t + 256] = acc[i][1];
    }
}

// ---------------- CSR build --------------------------------------------------
__global__ void k_hist(const int* __restrict__ ei) {
    int e = blockIdx.x * blockDim.x + threadIdx.x;
    if (e >= N_EDGES) return;
    atomicAdd(&g_deg[__ldg(&ei[N_EDGES + e])], 1);
}

__global__ void k_scan1() {
    __shared__ int sh[1024];
    int t = threadIdx.x;
    int i = blockIdx.x * 1024 + t;
    int v = (i < N_SCAN) ? g_deg[i] : 0;
    int orig = v;
    sh[t] = v;
    __syncthreads();
#pragma unroll
    for (int d = 1; d < 1024; d <<= 1) {
        int u = (t >= d) ? sh[t - d] : 0;
        __syncthreads();
        sh[t] += u;
        __syncthreads();
    }
    if (i < N_SCAN) g_off[i] = sh[t] - orig;
    if (t == 1023) g_bsum[blockIdx.x] = sh[1023];
}

__global__ void k_scan2() {
    __shared__ int sh[128];
    int t = threadIdx.x;
    int v = (t < SCAN_NBLK) ? g_bsum[t] : 0;
    sh[t] = v;
    __syncthreads();
#pragma unroll
    for (int d = 1; d < 128; d <<= 1) {
        int u = (t >= d) ? sh[t - d] : 0;
        __syncthreads();
        sh[t] += u;
        __syncthreads();
    }
    if (t < SCAN_NBLK) g_bsum[t] = sh[t] - v;
}

__global__ void k_scan3() {
    int i = blockIdx.x * blockDim.x + threadIdx.x;
    if (i >= N_SCAN) return;
    int o = g_off[i] + g_bsum[i >> 10];
    g_off[i] = o;
    if (i < N_NODES) g_cur[i] = o;
}

__global__ void k_fill(const int* __restrict__ ei) {
    int e = blockIdx.x * blockDim.x + threadIdx.x;
    if (e >= N_EDGES) return;
    int d = __ldg(&ei[N_EDGES + e]);
    int pos = atomicAdd(&g_cur[d], 1);
    g_csr[pos] = __ldg(&ei[e]);
}

// ---------------- layer-1 gather (row-range), fp16 output ---------------------
__global__ void k_gather1(const int* __restrict__ x, const float* __restrict__ E,
                          __half* __restrict__ Y, int rbase, int rend) {
    int row = rbase + blockIdx.x * 2 + (threadIdx.x >> 7);
    int cq  = threadIdx.x & 127;
    if (row >= rend) return;
    int tok = __ldg(&x[row]);
    float4 acc = __ldg((const float4*)E + (size_t)tok * 128 + cq);
    int e0 = __ldg(&g_off[row]), e1 = __ldg(&g_off[row + 1]);
    for (int e = e0; e < e1; e++) {
        int s  = __ldg(&g_csr[e]);
        int tk = __ldg(&x[s]);
        float4 v = __ldg((const float4*)E + (size_t)tk * 128 + cq);
        acc.x += v.x; acc.y += v.y; acc.z += v.z; acc.w += v.w;
    }
    sth4(Y, (size_t)row * 128 + cq, acc);
}

// ---------------- layer-2 gather (row-range): fp16 in, fp16 A out --------------
__global__ void k_gather2(const __half* __restrict__ Y,
                          const float* __restrict__ cA, const float* __restrict__ cB,
                          __half* __restrict__ A, int rbase, int rend) {
    int row = rbase + blockIdx.x * 2 + (threadIdx.x >> 7);
    int cq  = threadIdx.x & 127;
    if (row >= rend) return;
    float4 a = __ldg((const float4*)cA + cq);
    float4 b = __ldg((const float4*)cB + cq);
    float4 y = ldh4(Y, (size_t)row * 128 + cq);
    float4 acc;
    acc.x = fmaxf(fmaf(y.x, a.x, b.x), 0.f);
    acc.y = fmaxf(fmaf(y.y, a.y, b.y), 0.f);
    acc.z = fmaxf(fmaf(y.z, a.z, b.z), 0.f);
    acc.w = fmaxf(fmaf(y.w, a.w, b.w), 0.f);
    int e0 = __ldg(&g_off[row]), e1 = __ldg(&g_off[row + 1]);
    for (int e = e0; e < e1; e++) {
        int s = __ldg(&g_csr[e]);
        float4 v = ldh4(Y, (size_t)s * 128 + cq);
        acc.x += fmaxf(fmaf(v.x, a.x, b.x), 0.f);
        acc.y += fmaxf(fmaf(v.y, a.y, b.y), 0.f);
        acc.z += fmaxf(fmaf(v.z, a.z, b.z), 0.f);
        acc.w += fmaxf(fmaf(v.w, a.w, b.w), 0.f);
    }
    sth4(A, (size_t)row * 128 + cq, acc);
}

// ---------------- BN stats (row-range) / finalize ------------------------------
__global__ void k_colstats(const __half* __restrict__ Y, float* __restrict__ stats,
                           int rbase, int rend) {
    int c  = threadIdx.x;
    int r0 = rbase + blockIdx.x * CS_ROWS;
    int r1 = min(r0 + CS_ROWS, rend);
    float s = 0.f, s2 = 0.f;
    for (int r = r0; r < r1; r++) {
        float v = __half2float(__ldg(Y + (size_t)r * HIDDEN + c));
        s += v; s2 += v * v;
    }
    atomicAdd(&stats[c], s);
    atomicAdd(&stats[HIDDEN + c], s2);
}

__global__ void k_finalize(const float* __restrict__ stats, const float* __restrict__ g,
                           const float* __restrict__ be,
                           float* __restrict__ coefA, float* __restrict__ coefB) {
    int c = threadIdx.x;
    float inv_n = 1.f / (float)N_NODES;
    float mu  = stats[c] * inv_n;
    float var = fmaxf(stats[HIDDEN + c] * inv_n - mu * mu, 0.f);
    float sc  = rsqrtf(var + BN_EPS) * g[c];
    coefA[c] = sc;
    coefB[c] = be[c] - mu * sc;
}

// ---------------- pooling (fused layer-2 BN + ReLU), fp16 input ----------------
__global__ void k_pool_bn(const __half* __restrict__ Y, const int* __restrict__ batch,
                          const float* __restrict__ cA, const float* __restrict__ cB) {
    const int NPB = 256;
    __shared__ int sb[NPB];
    int t     = threadIdx.x;
    int start = blockIdx.x * NPB;
    int end   = min(start + NPB, N_NODES);
    int n     = end - start;
    if (n <= 0) return;
    for (int i = t; i < n; i += 512) sb[i] = batch[start + i];
    __syncthreads();
    float a = __ldg(&cA[t]);
    float b = __ldg(&cB[t]);
    float acc = 0.f;
    int cur = sb[0], run = 0;
    for (int i = 0; i < n; i++) {
        int bg = sb[i];
        if (bg != cur) {
            atomicAdd(&g_pooled[(size_t)cur * HIDDEN + t], acc);
            if (t == 0) atomicAdd(&g_cnt[cur], (float)run);
            acc = 0.f; run = 0; cur = bg;
        }
        float v = __half2float(__ldg(Y + (size_t)(start + i) * HIDDEN + t));
        acc += fmaxf(fmaf(v, a, b), 0.f);
        run++;
    }
    atomicAdd(&g_pooled[(size_t)cur * HIDDEN + t], acc);
    if (t == 0) atomicAdd(&g_cnt[cur], (float)run);
}

__global__ void k_lin1(const float* __restrict__ Wl1, const float* __restrict__ bl1) {
    __shared__ float ps[HIDDEN];
    int g = blockIdx.x, j = threadIdx.x;
    ps[j]       = g_pooled[(size_t)g * HIDDEN + j];
    ps[j + 256] = g_pooled[(size_t)g * HIDDEN + j + 256];
    __syncthreads();
    float inv = 1.f / fmaxf(g_cnt[g], 1.f);
    float acc = 0.f;
#pragma unroll 8
    for (int k = 0; k < HIDDEN; k++)
        acc += ps[k] * __ldg(&Wl1[(size_t)k * HALF_H + j]);
    g_z[(size_t)g * HALF_H + j] = fmaxf(acc * inv + bl1[j], 0.f);
}

__global__ void k_lin2(const float* __restrict__ Wl2, const float* __restrict__ bl2,
                       float* __restrict__ out) {
    __shared__ float zs[HALF_H];
    int g = blockIdx.x, j = threadIdx.x;
    zs[j]       = g_z[(size_t)g * HALF_H + j];
    zs[j + 128] = g_z[(size_t)g * HALF_H + j + 128];
    __syncthreads();
    float acc = bl2[j];
#pragma unroll 8
    for (int k = 0; k < HALF_H; k++)
        acc += zs[k] * __ldg(&Wl2[(size_t)k * OUT_DIM + j]);
    out[(size_t)g * OUT_DIM + j] = acc;
}

// ---------------- weight convert: W2[K][N] -> Wt fp16 [N][K] --------------------
__global__ void k_conv_W(const float* __restrict__ W, __half* __restrict__ Wt) {
    int idx = blockIdx.x * blockDim.x + threadIdx.x;
    if (idx >= HIDDEN * HIDDEN) return;
    int n = idx >> 9;
    int k = idx & 511;
    Wt[idx] = __float2half_rn(__ldg(&W[(size_t)k * HIDDEN + n]));
}

// ---------------- fp16 mma GEMM + fused BN stats (2-stage) ----------------------
#define GT       256
#define OFF_A    0
#define OFF_B    8192
#define STAGE    16384
#define G_SMEM   (2 * STAGE)

__global__ __launch_bounds__(GT)
void k_mma_gemm(const __half* __restrict__ A, const __half* __restrict__ B,
                __half* __restrict__ C, float* __restrict__ stats, int K, int rbase) {
    extern __shared__ char smem[];
    __shared__ float ss[128];
    __shared__ float qq[128];
    uint32_t sb = smem_u32(smem);
    int tid  = threadIdx.x;
    int lane = tid & 31;
    int wid  = tid >> 5;
    int wm   = (wid & 3) * 32;
    int wn   = (wid >> 2) * 64;
    int row0 = rbase + blockIdx.y * 128;
    int col0 = blockIdx.x * 128;

    if (tid < 128) { ss[tid] = 0.f; qq[tid] = 0.f; }

    float acc[2][8][4];
#pragma unroll
    for (int i = 0; i < 2; i++)
#pragma unroll
        for (int j = 0; j < 8; j++)
#pragma unroll
            for (int l = 0; l < 4; l++) acc[i][j][l] = 0.f;

    int nch = K >> 5;

    auto load_chunk = [&](int i, int buf) {
        int k0 = i << 5;
        uint32_t base = sb + buf * STAGE;
#pragma unroll
        for (int p = 0; p < 2; p++) {
            int u = tid + p * GT;          // 0..511
            int r = u >> 2, q = u & 3;
            uint32_t so = swz(r, q);
            size_t ga = (size_t)(row0 + r) * K + k0 + q * 8;
            size_t gb = (size_t)(col0 + r) * K + k0 + q * 8;
            cp_async16(base + OFF_A + so, A + ga);
            cp_async16(base + OFF_B + so, B + gb);
        }
    };

    load_chunk(0, 0);
    CP_COMMIT();

    int a_row = (lane & 15);
    int a_qh  = (lane >> 4);
    int b_row = (lane & 7) + ((lane >> 4) << 3);
    int b_qh  = (lane >> 3) & 1;

    for (int i = 0; i < nch; i++) {
        if (i + 1 < nch) {
            load_chunk(i + 1, (i + 1) & 1);
            CP_COMMIT();
            CP_WAIT(1);
        } else {
            CP_WAIT(0);
        }
        __syncthreads();
        uint32_t stg = sb + (i & 1) * STAGE;

#pragma unroll
        for (int s = 0; s < 2; s++) {
            uint32_t ah[2][4];
#pragma unroll
            for (int mt = 0; mt < 2; mt++) {
                int r = wm + mt * 16 + a_row;
                int q = a_qh + 2 * s;
                ldm4(ah[mt], stg + OFF_A + swz(r, q));
            }
#pragma unroll
            for (int pr = 0; pr < 4; pr++) {
                int r = wn + pr * 16 + b_row;
                int q = b_qh + 2 * s;
                uint32_t bh[4];
                ldm4(bh, stg + OFF_B + swz(r, q));
#pragma unroll
                for (int mt = 0; mt < 2; mt++) {
#pragma unroll
                    for (int h = 0; h < 2; h++) {
                        mma_fp16(acc[mt][pr * 2 + h], ah[mt], bh + 2 * h);
                    }
                }
            }
        }
        __syncthreads();
    }

    int g   = lane >> 2;
    int tig = lane & 3;
#pragma unroll
    for (int mt = 0; mt < 2; mt++) {
        int r0 = row0 + wm + mt * 16 + g;
        int r1 = r0 + 8;
#pragma unroll
        for (int nt = 0; nt < 8; nt++) {
            int col = col0 + wn + nt * 8 + 2 * tig;
            if (r0 < N_NODES) {
                __half2 o = __floats2half2_rn(acc[mt][nt][0], acc[mt][nt][1]);
                *(__half2*)(C + (size_t)r0 * HIDDEN + col) = o;
            }
            if (r1 < N_NODES) {
                __half2 o = __floats2half2_rn(acc[mt][nt][2], acc[mt][nt][3]);
                *(__half2*)(C + (size_t)r1 * HIDDEN + col) = o;
            }
        }
    }
#pragma unroll
    for (int nt = 0; nt < 8; nt++) {
        float s0 = 0.f, q0 = 0.f, s1 = 0.f, q1 = 0.f;
#pragma unroll
        for (int mt = 0; mt < 2; mt++) {
            float c0 = acc[mt][nt][0], c1 = acc[mt][nt][1];
            float c2 = acc[mt][nt][2], c3 = acc[mt][nt][3];
            s0 += c0 + c2;  q0 += c0 * c0 + c2 * c2;
            s1 += c1 + c3;  q1 += c1 * c1 + c3 * c3;
        }
#pragma unroll
        for (int o = 4; o < 32; o <<= 1) {
            s0 += __shfl_xor_sync(0xFFFFFFFF, s0, o);
            q0 += __shfl_xor_sync(0xFFFFFFFF, q0, o);
            s1 += __shfl_xor_sync(0xFFFFFFFF, s1, o);
            q1 += __shfl_xor_sync(0xFFFFFFFF, q1, o);
        }
        if (lane < 4) {
            int c = wn + nt * 8 + 2 * lane;
            atomicAdd(&ss[c], s0);     atomicAdd(&qq[c], q0);
            atomicAdd(&ss[c + 1], s1); atomicAdd(&qq[c + 1], q1);
        }
    }
    __syncthreads();
    if (tid < 128) {
        atomicAdd(&stats[col0 + tid], ss[tid]);
        atomicAdd(&stats[HIDDEN + col0 + tid], qq[tid]);
    }
}

// ---------------- launch ----------------------------------------------------------
extern "C" void kernel_launch(void* const* d_in, const int* in_sizes, int n_in,
                              void* d_out, int out_size) {
    const int*   x     = (const int*)d_in[0];
    const int*   ei    = (const int*)d_in[1];
    const int*   batch = (const int*)d_in[2];
    const float* emb   = (const float*)d_in[3];
    const float* W1    = (const float*)d_in[4];
    const float* g1    = (const float*)d_in[6];
    const float* be1   = (const float*)d_in[7];
    const float* W2    = (const float*)d_in[8];
    const float* g2    = (const float*)d_in[10];
    const float* be2   = (const float*)d_in[11];
    const float* Wl1   = (const float*)d_in[12];
    const float* bl1   = (const float*)d_in[13];
    const float* Wl2   = (const float*)d_in[14];
    const float* bl2   = (const float*)d_in[15];
    float* out = (float*)d_out;

    static bool s_init = false;
    static cudaStream_t sA, sB, sC;
    static cudaEvent_t evFork, evA, evB, evG1a, evCS, evG2a, evGEMM;
    if (!s_init) {
        cudaFuncSetAttribute(k_mma_gemm, cudaFuncAttributeMaxDynamicSharedMemorySize, G_SMEM);
        cudaStreamCreateWithFlags(&sA, cudaStreamNonBlocking);
        cudaStreamCreateWithFlags(&sB, cudaStreamNonBlocking);
        cudaStreamCreateWithFlags(&sC, cudaStreamNonBlocking);
        cudaEventCreateWithFlags(&evFork, cudaEventDisableTiming);
        cudaEventCreateWithFlags(&evA,    cudaEventDisableTiming);
        cudaEventCreateWithFlags(&evB,    cudaEventDisableTiming);
        cudaEventCreateWithFlags(&evG1a,  cudaEventDisableTiming);
        cudaEventCreateWithFlags(&evCS,   cudaEventDisableTiming);
        cudaEventCreateWithFlags(&evG2a,  cudaEventDisableTiming);
        cudaEventCreateWithFlags(&evGEMM, cudaEventDisableTiming);
        s_init = true;
    }

    float *p_E, *p_stats, *p_coefA, *p_coefB, *p_pooled, *p_cnt;
    __half *p_y, *p_A, *p_Wt;
    int *p_deg;
    cudaGetSymbolAddress((void**)&p_E,     g_E);
    cudaGetSymbolAddress((void**)&p_y,     g_y);
    cudaGetSymbolAddress((void**)&p_stats, g_stats);
    cudaGetSymbolAddress((void**)&p_coefA, g_coefA);
    cudaGetSymbolAddress((void**)&p_coefB, g_coefB);
    cudaGetSymbolAddress((void**)&p_pooled,g_pooled);
    cudaGetSymbolAddress((void**)&p_cnt,   g_cnt);
    cudaGetSymbolAddress((void**)&p_deg,   g_deg);
    cudaGetSymbolAddress((void**)&p_A,     g_A);
    cudaGetSymbolAddress((void**)&p_Wt,    g_Wt);

    // fork side streams off the capture (NULL) stream
    cudaEventRecord(evFork, 0);
    cudaStreamWaitEvent(sA, evFork, 0);
    cudaStreamWaitEvent(sB, evFork, 0);
    cudaStreamWaitEvent(sC, evFork, 0);

    // main stream: CSR chain
    cudaMemsetAsync(p_deg,    0, N_SCAN * sizeof(int));
    cudaMemsetAsync(p_stats,  0, 4 * HIDDEN * sizeof(float));
    k_hist<<<(N_EDGES + 255) / 256, 256>>>(ei);
    k_scan1<<<SCAN_NBLK, 1024>>>();
    k_scan2<<<1, 128>>>();
    k_scan3<<<(N_SCAN + 255) / 256, 256>>>();
    k_fill<<<(N_EDGES + 255) / 256, 256>>>(ei);

    // stream A: E' = emb @ W1
    k_gemm_emb<<<VOCAB / 4, 256, 0, sA>>>(emb, W1, p_E);
    cudaEventRecord(evA, sA);

    // stream B: W2 convert + pool resets
    cudaMemsetAsync(p_pooled, 0, (size_t)N_GRAPHS * HIDDEN * sizeof(float), sB);
    cudaMemsetAsync(p_cnt,    0, N_GRAPHS * sizeof(float), sB);
    k_conv_W<<<(HIDDEN * HIDDEN + 255) / 256, 256, 0, sB>>>(W2, p_Wt);
    cudaEventRecord(evB, sB);

    cudaStreamWaitEvent(0, evA, 0);

    // ---- layer 1: gather half0; colstats(half0) overlaps gather half1
    k_gather1<<<HALF_R / 2, 256>>>(x, p_E, p_y, 0, HALF_R);
    cudaEventRecord(evG1a, 0);
    cudaStreamWaitEvent(sC, evG1a, 0);
    k_colstats<<<(HALF_R + CS_ROWS - 1) / CS_ROWS, 512, 0, sC>>>(p_y, p_stats, 0, HALF_R);
    cudaEventRecord(evCS, sC);
    k_gather1<<<(N_NODES - HALF_R + 1) / 2, 256>>>(x, p_E, p_y, HALF_R, N_NODES);
    k_colstats<<<(N_NODES - HALF_R + CS_ROWS - 1) / CS_ROWS, 512>>>(p_y, p_stats,
                                                                    HALF_R, N_NODES);
    cudaStreamWaitEvent(0, evCS, 0);
    k_finalize<<<1, HIDDEN>>>(p_stats, g1, be1, p_coefA, p_coefB);

    // ---- layer 2: gather half0; GEMM(half0) on sC overlaps gather half1
    k_gather2<<<HALF_R / 2, 256>>>(p_y, p_coefA, p_coefB, p_A, 0, HALF_R);
    cudaEventRecord(evG2a, 0);
    cudaStreamWaitEvent(sC, evG2a, 0);
    cudaStreamWaitEvent(sC, evB, 0);
    {
        dim3 grid(HIDDEN / 128, HALF_R / 128);
        k_mma_gemm<<<grid, GT, G_SMEM, sC>>>(p_A, p_Wt, p_y,
                                             p_stats + 2 * HIDDEN, HIDDEN, 0);
    }
    cudaEventRecord(evGEMM, sC);
    k_gather2<<<(N_NODES - HALF_R + 1) / 2, 256>>>(p_y, p_coefA, p_coefB,
                                                   p_A, HALF_R, N_NODES);
    cudaStreamWaitEvent(0, evB, 0);
    {
        dim3 grid(HIDDEN / 128, (ROWSP - HALF_R) / 128);
        k_mma_gemm<<<grid, GT, G_SMEM>>>(p_A, p_Wt, p_y,
                                         p_stats + 2 * HIDDEN, HIDDEN, HALF_R);
    }
    cudaStreamWaitEvent(0, evGEMM, 0);
    k_finalize<<<1, HIDDEN>>>(p_stats + 2 * HIDDEN, g2, be2,
                              p_coefA + HIDDEN, p_coefB + HIDDEN);

    // ---- pooling (fused layer-2 BN+ReLU) + head
    k_pool_bn<<<(N_NODES + 255) / 256, 512>>>(p_y, batch, p_coefA + HIDDEN, p_coefB + HIDDEN);
    k_lin1<<<N_GRAPHS, HALF_H>>>(Wl1, bl1);
    k_lin2<<<N_GRAPHS, OUT_DIM>>>(Wl2, bl2, out);
}

// round 15
// speedup vs baseline: 1.3592x; 1.3592x over previous
#include <cuda_runtime.h>
#include <cuda_fp16.h>
#include <cstdint>

#define N_NODES  100000
#define N_SCAN   (N_NODES + 1)
#define ROWSP    100096          // padded to multiple of 128
#define HALF_R   50048           // = 391 * 128
#define N_EDGES  250000
#define N_GRAPHS 512
#define VOCAB    1000
#define EMBED    256
#define HIDDEN   512
#define HALF_H   256
#define OUT_DIM  128
#define BN_EPS   1e-5f
#define SCAN_NBLK ((N_SCAN + 1023) / 1024)   // 98
#define CS_ROWS  338

// ---------------- scratch (device globals; no allocation allowed) ----------
__device__ float  g_E   [(size_t)VOCAB * HIDDEN];
__device__ __half g_y   [(size_t)N_NODES * HIDDEN];   // fp16 activations (y1, then y2)
__device__ float  g_stats[4 * HIDDEN];
__device__ float  g_coefA[2 * HIDDEN];
__device__ float  g_coefB[2 * HIDDEN];
__device__ float  g_pooled[N_GRAPHS * HIDDEN];
__device__ float  g_cnt[N_GRAPHS];
__device__ float  g_z[N_GRAPHS * HALF_H];
// CSR of in-edges (rebuilt per call)
__device__ int g_deg[N_SCAN];
__device__ int g_off[N_SCAN];
__device__ int g_cur[N_NODES];
__device__ int g_bsum[SCAN_NBLK];
__device__ int g_csr[N_EDGES];
// fp16 GEMM operands; pad rows never written -> stay zero
__device__ __half g_A [(size_t)ROWSP * HIDDEN];
__device__ __half g_Wt[HIDDEN * HIDDEN];              // [N][K] K-major

// ---------------- PTX helpers ----------------------------------------------
__device__ __forceinline__ uint32_t smem_u32(const void* p) {
    uint32_t a;
    asm("{ .reg .u64 t; cvta.to.shared.u64 t, %1; cvt.u32.u64 %0, t; }" : "=r"(a) : "l"(p));
    return a;
}
__device__ __forceinline__ void cp_async16(uint32_t dst, const void* src) {
    asm volatile("cp.async.cg.shared.global [%0], [%1], 16;" :: "r"(dst), "l"(src));
}
#define CP_COMMIT()  asm volatile("cp.async.commit_group;" ::: "memory")
#define CP_WAIT(n)   asm volatile("cp.async.wait_group %0;" :: "n"(n) : "memory")

__device__ __forceinline__ void ldm4(uint32_t* r, uint32_t addr) {
    asm volatile("ldmatrix.sync.aligned.m8n8.x4.shared.b16 {%0,%1,%2,%3}, [%4];"
                 : "=r"(r[0]), "=r"(r[1]), "=r"(r[2]), "=r"(r[3]) : "r"(addr));
}
__device__ __forceinline__ void mma_fp16(float* c, const uint32_t* a, const uint32_t* b) {
    asm volatile(
        "mma.sync.aligned.m16n8k16.row.col.f32.f16.f16.f32 "
        "{%0,%1,%2,%3}, {%4,%5,%6,%7}, {%8,%9}, {%0,%1,%2,%3};"
        : "+f"(c[0]), "+f"(c[1]), "+f"(c[2]), "+f"(c[3])
        : "r"(a[0]), "r"(a[1]), "r"(a[2]), "r"(a[3]), "r"(b[0]), "r"(b[1]));
}
__device__ __forceinline__ uint32_t swz(int row, int q) {
    return (uint32_t)(row * 64 + ((q ^ ((row >> 1) & 3)) << 4));
}
// load 4 consecutive halves (8B) as float4; idx in 4-half units
__device__ __forceinline__ float4 ldh4(const __half* Y, size_t idx) {
    uint2 raw = __ldg((const uint2*)Y + idx);
    __half2 a = *reinterpret_cast<__half2*>(&raw.x);
    __half2 b = *reinterpret_cast<__half2*>(&raw.y);
    float2 fa = __half22float2(a), fb = __half22float2(b);
    return make_float4(fa.x, fa.y, fb.x, fb.y);
}
__device__ __forceinline__ void sth4(__half* Y, size_t idx, float4 v) {
    __half2 h0 = __floats2half2_rn(v.x, v.y);
    __half2 h1 = __floats2half2_rn(v.z, v.w);
    uint2 o;
    o.x = *reinterpret_cast<uint32_t*>(&h0);
    o.y = *reinterpret_cast<uint32_t*>(&h1);
    ((uint2*)Y)[idx] = o;
}

// ---------------- tiny GEMM: E' = emb @ W1 ----------------------------------
__global__ void k_gemm_emb(const float* __restrict__ emb, const float* __restrict__ W1,
                           float* __restrict__ E) {
    __shared__ float er[4][EMBED];
    int r0 = blockIdx.x * 4, t = threadIdx.x;
#pragma unroll
    for (int i = 0; i < 4; i++) er[i][t] = emb[(size_t)(r0 + i) * EMBED + t];
    __syncthreads();
    float acc[4][2] = {};
    for (int k = 0; k < EMBED; k++) {
        float w0 = __ldg(&W1[(size_t)k * HIDDEN + t]);
        float w1 = __ldg(&W1[(size_t)k * HIDDEN + t + 256]);
#pragma unroll
        for (int i = 0; i < 4; i++) {
            acc[i][0] = fmaf(er[i][k], w0, acc[i][0]);
            acc[i][1] = fmaf(er[i][k], w1, acc[i][1]);
        }
    }
#pragma unroll
    for (int i = 0; i < 4; i++) {
        E[(size_t)(r0 + i) * HIDDEN + t]       = acc[i][0];
        E[(size_t)(r0 + i) * HIDDEN + t + 256] = acc[i][1];
    }
}

// ---------------- CSR build --------------------------------------------------
__global__ void k_hist(const int* __restrict__ ei) {
    int e = blockIdx.x * blockDim.x + threadIdx.x;
    if (e >= N_EDGES) return;
    atomicAdd(&g_deg[__ldg(&ei[N_EDGES + e])], 1);
}

__global__ void k_scan1() {
    __shared__ int sh[1024];
    int t = threadIdx.x;
    int i = blockIdx.x * 1024 + t;
    int v = (i < N_SCAN) ? g_deg[i] : 0;
    int orig = v;
    sh[t] = v;
    __syncthreads();
#pragma unroll
    for (int d = 1; d < 1024; d <<= 1) {
        int u = (t >= d) ? sh[t - d] : 0;
        __syncthreads();
        sh[t] += u;
        __syncthreads();
    }
    if (i < N_SCAN) g_off[i] = sh[t] - orig;
    if (t == 1023) g_bsum[blockIdx.x] = sh[1023];
}

__global__ void k_scan2() {
    __shared__ int sh[128];
    int t = threadIdx.x;
    int v = (t < SCAN_NBLK) ? g_bsum[t] : 0;
    sh[t] = v;
    __syncthreads();
#pragma unroll
    for (int d = 1; d < 128; d <<= 1) {
        int u = (t >= d) ? sh[t - d] : 0;
        __syncthreads();
        sh[t] += u;
        __syncthreads();
    }
    if (t < SCAN_NBLK) g_bsum[t] = sh[t] - v;
}

__global__ void k_scan3() {
    int i = blockIdx.x * blockDim.x + threadIdx.x;
    if (i >= N_SCAN) return;
    int o = g_off[i] + g_bsum[i >> 10];
    g_off[i] = o;
    if (i < N_NODES) g_cur[i] = o;
}

__global__ void k_fill(const int* __restrict__ ei) {
    int e = blockIdx.x * blockDim.x + threadIdx.x;
    if (e >= N_EDGES) return;
    int d = __ldg(&ei[N_EDGES + e]);
    int pos = atomicAdd(&g_cur[d], 1);
    g_csr[pos] = __ldg(&ei[e]);
}

// ---------------- layer-1 gather (row-range), fp16 output ---------------------
__global__ void k_gather1(const int* __restrict__ x, const float* __restrict__ E,
                          __half* __restrict__ Y, int rbase, int rend) {
    int row = rbase + blockIdx.x * 2 + (threadIdx.x >> 7);
    int cq  = threadIdx.x & 127;
    if (row >= rend) return;
    int tok = __ldg(&x[row]);
    float4 acc = __ldg((const float4*)E + (size_t)tok * 128 + cq);
    int e0 = __ldg(&g_off[row]), e1 = __ldg(&g_off[row + 1]);
    for (int e = e0; e < e1; e++) {
        int s  = __ldg(&g_csr[e]);
        int tk = __ldg(&x[s]);
        float4 v = __ldg((const float4*)E + (size_t)tk * 128 + cq);
        acc.x += v.x; acc.y += v.y; acc.z += v.z; acc.w += v.w;
    }
    sth4(Y, (size_t)row * 128 + cq, acc);
}

// ---------------- layer-2 gather: fp16 in, fp16 A out --------------------------
__global__ void k_gather2(const __half* __restrict__ Y,
                          const float* __restrict__ cA, const float* __restrict__ cB,
                          __half* __restrict__ A) {
    int row = blockIdx.x * 2 + (threadIdx.x >> 7);
    int cq  = threadIdx.x & 127;
    if (row >= N_NODES) return;
    float4 a = __ldg((const float4*)cA + cq);
    float4 b = __ldg((const float4*)cB + cq);
    float4 y = ldh4(Y, (size_t)row * 128 + cq);
    float4 acc;
    acc.x = fmaxf(fmaf(y.x, a.x, b.x), 0.f);
    acc.y = fmaxf(fmaf(y.y, a.y, b.y), 0.f);
    acc.z = fmaxf(fmaf(y.z, a.z, b.z), 0.f);
    acc.w = fmaxf(fmaf(y.w, a.w, b.w), 0.f);
    int e0 = __ldg(&g_off[row]), e1 = __ldg(&g_off[row + 1]);
    for (int e = e0; e < e1; e++) {
        int s = __ldg(&g_csr[e]);
        float4 v = ldh4(Y, (size_t)s * 128 + cq);
        acc.x += fmaxf(fmaf(v.x, a.x, b.x), 0.f);
        acc.y += fmaxf(fmaf(v.y, a.y, b.y), 0.f);
        acc.z += fmaxf(fmaf(v.z, a.z, b.z), 0.f);
        acc.w += fmaxf(fmaf(v.w, a.w, b.w), 0.f);
    }
    sth4(A, (size_t)row * 128 + cq, acc);
}

// ---------------- BN stats (row-range) / finalize ------------------------------
__global__ void k_colstats(const __half* __restrict__ Y, float* __restrict__ stats,
                           int rbase, int rend) {
    int c  = threadIdx.x;
    int r0 = rbase + blockIdx.x * CS_ROWS;
    int r1 = min(r0 + CS_ROWS, rend);
    float s = 0.f, s2 = 0.f;
    for (int r = r0; r < r1; r++) {
        float v = __half2float(__ldg(Y + (size_t)r * HIDDEN + c));
        s += v; s2 += v * v;
    }
    atomicAdd(&stats[c], s);
    atomicAdd(&stats[HIDDEN + c], s2);
}

__global__ void k_finalize(const float* __restrict__ stats, const float* __restrict__ g,
                           const float* __restrict__ be,
                           float* __restrict__ coefA, float* __restrict__ coefB) {
    int c = threadIdx.x;
    float inv_n = 1.f / (float)N_NODES;
    float mu  = stats[c] * inv_n;
    float var = fmaxf(stats[HIDDEN + c] * inv_n - mu * mu, 0.f);
    float sc  = rsqrtf(var + BN_EPS) * g[c];
    coefA[c] = sc;
    coefB[c] = be[c] - mu * sc;
}

// ---------------- pooling (fused layer-2 BN + ReLU), fp16 input ----------------
__global__ void k_pool_bn(const __half* __restrict__ Y, const int* __restrict__ batch,
                          const float* __restrict__ cA, const float* __restrict__ cB) {
    const int NPB = 256;
    __shared__ int sb[NPB];
    int t     = threadIdx.x;
    int start = blockIdx.x * NPB;
    int end   = min(start + NPB, N_NODES);
    int n     = end - start;
    if (n <= 0) return;
    for (int i = t; i < n; i += 512) sb[i] = batch[start + i];
    __syncthreads();
    float a = __ldg(&cA[t]);
    float b = __ldg(&cB[t]);
    float acc = 0.f;
    int cur = sb[0], run = 0;
    for (int i = 0; i < n; i++) {
        int bg = sb[i];
        if (bg != cur) {
            atomicAdd(&g_pooled[(size_t)cur * HIDDEN + t], acc);
            if (t == 0) atomicAdd(&g_cnt[cur], (float)run);
            acc = 0.f; run = 0; cur = bg;
        }
        float v = __half2float(__ldg(Y + (size_t)(start + i) * HIDDEN + t));
        acc += fmaxf(fmaf(v, a, b), 0.f);
        run++;
    }
    atomicAdd(&g_pooled[(size_t)cur * HIDDEN + t], acc);
    if (t == 0) atomicAdd(&g_cnt[cur], (float)run);
}

__global__ void k_lin1(const float* __restrict__ Wl1, const float* __restrict__ bl1) {
    __shared__ float ps[HIDDEN];
    int g = blockIdx.x, j = threadIdx.x;
    ps[j]       = g_pooled[(size_t)g * HIDDEN + j];
    ps[j + 256] = g_pooled[(size_t)g * HIDDEN + j + 256];
    __syncthreads();
    float inv = 1.f / fmaxf(g_cnt[g], 1.f);
    float acc = 0.f;
#pragma unroll 8
    for (int k = 0; k < HIDDEN; k++)
        acc += ps[k] * __ldg(&Wl1[(size_t)k * HALF_H + j]);
    g_z[(size_t)g * HALF_H + j] = fmaxf(acc * inv + bl1[j], 0.f);
}

__global__ void k_lin2(const float* __restrict__ Wl2, const float* __restrict__ bl2,
                       float* __restrict__ out) {
    __shared__ float zs[HALF_H];
    int g = blockIdx.x, j = threadIdx.x;
    zs[j]       = g_z[(size_t)g * HALF_H + j];
    zs[j + 128] = g_z[(size_t)g * HALF_H + j + 128];
    __syncthreads();
    float acc = bl2[j];
#pragma unroll 8
    for (int k = 0; k < HALF_H; k++)
        acc += zs[k] * __ldg(&Wl2[(size_t)k * OUT_DIM + j]);
    out[(size_t)g * OUT_DIM + j] = acc;
}

// ---------------- weight convert: W2[K][N] -> Wt fp16 [N][K] --------------------
__global__ void k_conv_W(const float* __restrict__ W, __half* __restrict__ Wt) {
    int idx = blockIdx.x * blockDim.x + threadIdx.x;
    if (idx >= HIDDEN * HIDDEN) return;
    int n = idx >> 9;
    int k = idx & 511;
    Wt[idx] = __float2half_rn(__ldg(&W[(size_t)k * HIDDEN + n]));
}

// ---------------- fp16 mma GEMM + fused BN stats (2-stage) ----------------------
#define GT       256
#define OFF_A    0
#define OFF_B    8192
#define STAGE    16384
#define G_SMEM   (2 * STAGE)

__global__ __launch_bounds__(GT)
void k_mma_gemm(const __half* __restrict__ A, const __half* __restrict__ B,
                __half* __restrict__ C, float* __restrict__ stats, int K) {
    extern __shared__ char smem[];
    __shared__ float ss[128];
    __shared__ float qq[128];
    uint32_t sb = smem_u32(smem);
    int tid  = threadIdx.x;
    int lane = tid & 31;
    int wid  = tid >> 5;
    int wm   = (wid & 3) * 32;
    int wn   = (wid >> 2) * 64;
    int row0 = blockIdx.y * 128;
    int col0 = blockIdx.x * 128;

    if (tid < 128) { ss[tid] = 0.f; qq[tid] = 0.f; }

    float acc[2][8][4];
#pragma unroll
    for (int i = 0; i < 2; i++)
#pragma unroll
        for (int j = 0; j < 8; j++)
#pragma unroll
            for (int l = 0; l < 4; l++) acc[i][j][l] = 0.f;

    int nch = K >> 5;

    auto load_chunk = [&](int i, int buf) {
        int k0 = i << 5;
        uint32_t base = sb + buf * STAGE;
#pragma unroll
        for (int p = 0; p < 2; p++) {
            int u = tid + p * GT;          // 0..511
            int r = u >> 2, q = u & 3;
            uint32_t so = swz(r, q);
            size_t ga = (size_t)(row0 + r) * K + k0 + q * 8;
            size_t gb = (size_t)(col0 + r) * K + k0 + q * 8;
            cp_async16(base + OFF_A + so, A + ga);
            cp_async16(base + OFF_B + so, B + gb);
        }
    };

    load_chunk(0, 0);
    CP_COMMIT();

    int a_row = (lane & 15);
    int a_qh  = (lane >> 4);
    int b_row = (lane & 7) + ((lane >> 4) << 3);
    int b_qh  = (lane >> 3) & 1;

    for (int i = 0; i < nch; i++) {
        if (i + 1 < nch) {
            load_chunk(i + 1, (i + 1) & 1);
            CP_COMMIT();
            CP_WAIT(1);
        } else {
            CP_WAIT(0);
        }
        __syncthreads();
        uint32_t stg = sb + (i & 1) * STAGE;

#pragma unroll
        for (int s = 0; s < 2; s++) {
            uint32_t ah[2][4];
#pragma unroll
            for (int mt = 0; mt < 2; mt++) {
                int r = wm + mt * 16 + a_row;
                int q = a_qh + 2 * s;
                ldm4(ah[mt], stg + OFF_A + swz(r, q));
            }
#pragma unroll
            for (int pr = 0; pr < 4; pr++) {
                int r = wn + pr * 16 + b_row;
                int q = b_qh + 2 * s;
                uint32_t bh[4];
                ldm4(bh, stg + OFF_B + swz(r, q));
#pragma unroll
                for (int mt = 0; mt < 2; mt++) {
#pragma unroll
                    for (int h = 0; h < 2; h++) {
                        mma_fp16(acc[mt][pr * 2 + h], ah[mt], bh + 2 * h);
                    }
                }
            }
        }
        __syncthreads();
    }

    int g   = lane >> 2;
    int tig = lane & 3;
#pragma unroll
    for (int mt = 0; mt < 2; mt++) {
        int r0 = row0 + wm + mt * 16 + g;
        int r1 = r0 + 8;
#pragma unroll
        for (int nt = 0; nt < 8; nt++) {
            int col = col0 + wn + nt * 8 + 2 * tig;
            if (r0 < N_NODES) {
                __half2 o = __floats2half2_rn(acc[mt][nt][0], acc[mt][nt][1]);
                *(__half2*)(C + (size_t)r0 * HIDDEN + col) = o;
            }
            if (r1 < N_NODES) {
                __half2 o = __floats2half2_rn(acc[mt][nt][2], acc[mt][nt][3]);
                *(__half2*)(C + (size_t)r1 * HIDDEN + col) = o;
            }
        }
    }
#pragma unroll
    for (int nt = 0; nt < 8; nt++) {
        float s0 = 0.f, q0 = 0.f, s1 = 0.f, q1 = 0.f;
#pragma unroll
        for (int mt = 0; mt < 2; mt++) {
            float c0 = acc[mt][nt][0], c1 = acc[mt][nt][1];
            float c2 = acc[mt][nt][2], c3 = acc[mt][nt][3];
            s0 += c0 + c2;  q0 += c0 * c0 + c2 * c2;
            s1 += c1 + c3;  q1 += c1 * c1 + c3 * c3;
        }
#pragma unroll
        for (int o = 4; o < 32; o <<= 1) {
            s0 += __shfl_xor_sync(0xFFFFFFFF, s0, o);
            q0 += __shfl_xor_sync(0xFFFFFFFF, q0, o);
            s1 += __shfl_xor_sync(0xFFFFFFFF, s1, o);
            q1 += __shfl_xor_sync(0xFFFFFFFF, q1, o);
        }
        if (lane < 4) {
            int c = wn + nt * 8 + 2 * lane;
            atomicAdd(&ss[c], s0);     atomicAdd(&qq[c], q0);
            atomicAdd(&ss[c + 1], s1); atomicAdd(&qq[c + 1], q1);
        }
    }
    __syncthreads();
    if (tid < 128) {
        atomicAdd(&stats[col0 + tid], ss[tid]);
        atomicAdd(&stats[HIDDEN + col0 + tid], qq[tid]);
    }
}

// ---------------- launch ----------------------------------------------------------
extern "C" void kernel_launch(void* const* d_in, const int* in_sizes, int n_in,
                              void* d_out, int out_size) {
    const int*   x     = (const int*)d_in[0];
    const int*   ei    = (const int*)d_in[1];
    const int*   batch = (const int*)d_in[2];
    const float* emb   = (const float*)d_in[3];
    const float* W1    = (const float*)d_in[4];
    const float* g1    = (const float*)d_in[6];
    const float* be1   = (const float*)d_in[7];
    const float* W2    = (const float*)d_in[8];
    const float* g2    = (const float*)d_in[10];
    const float* be2   = (const float*)d_in[11];
    const float* Wl1   = (const float*)d_in[12];
    const float* bl1   = (const float*)d_in[13];
    const float* Wl2   = (const float*)d_in[14];
    const float* bl2   = (const float*)d_in[15];
    float* out = (float*)d_out;

    static bool s_init = false;
    static cudaStream_t sA, sB, sC;
    static cudaEvent_t evFork, evA, evB, evG1a, evCS;
    if (!s_init) {
        cudaFuncSetAttribute(k_mma_gemm, cudaFuncAttributeMaxDynamicSharedMemorySize, G_SMEM);
        cudaStreamCreateWithFlags(&sA, cudaStreamNonBlocking);
        cudaStreamCreateWithFlags(&sB, cudaStreamNonBlocking);
        cudaStreamCreateWithFlags(&sC, cudaStreamNonBlocking);
        cudaEventCreateWithFlags(&evFork, cudaEventDisableTiming);
        cudaEventCreateWithFlags(&evA,    cudaEventDisableTiming);
        cudaEventCreateWithFlags(&evB,    cudaEventDisableTiming);
        cudaEventCreateWithFlags(&evG1a,  cudaEventDisableTiming);
        cudaEventCreateWithFlags(&evCS,   cudaEventDisableTiming);
        s_init = true;
    }

    float *p_E, *p_stats, *p_coefA, *p_coefB, *p_pooled, *p_cnt;
    __half *p_y, *p_A, *p_Wt;
    int *p_deg;
    cudaGetSymbolAddress((void**)&p_E,     g_E);
    cudaGetSymbolAddress((void**)&p_y,     g_y);
    cudaGetSymbolAddress((void**)&p_stats, g_stats);
    cudaGetSymbolAddress((void**)&p_coefA, g_coefA);
    cudaGetSymbolAddress((void**)&p_coefB, g_coefB);
    cudaGetSymbolAddress((void**)&p_pooled,g_pooled);
    cudaGetSymbolAddress((void**)&p_cnt,   g_cnt);
    cudaGetSymbolAddress((void**)&p_deg,   g_deg);
    cudaGetSymbolAddress((void**)&p_A,     g_A);
    cudaGetSymbolAddress((void**)&p_Wt,    g_Wt);

    // fork side streams off the capture (NULL) stream
    cudaEventRecord(evFork, 0);
    cudaStreamWaitEvent(sA, evFork, 0);
    cudaStreamWaitEvent(sB, evFork, 0);
    cudaStreamWaitEvent(sC, evFork, 0);

    // main stream: CSR chain
    cudaMemsetAsync(p_deg,    0, N_SCAN * sizeof(int));
    cudaMemsetAsync(p_stats,  0, 4 * HIDDEN * sizeof(float));
    k_hist<<<(N_EDGES + 255) / 256, 256>>>(ei);
    k_scan1<<<SCAN_NBLK, 1024>>>();
    k_scan2<<<1, 128>>>();
    k_scan3<<<(N_SCAN + 255) / 256, 256>>>();
    k_fill<<<(N_EDGES + 255) / 256, 256>>>(ei);

    // stream A: E' = emb @ W1
    k_gemm_emb<<<VOCAB / 4, 256, 0, sA>>>(emb, W1, p_E);
    cudaEventRecord(evA, sA);

    // stream B: W2 convert + pool resets
    cudaMemsetAsync(p_pooled, 0, (size_t)N_GRAPHS * HIDDEN * sizeof(float), sB);
    cudaMemsetAsync(p_cnt,    0, N_GRAPHS * sizeof(float), sB);
    k_conv_W<<<(HIDDEN * HIDDEN + 255) / 256, 256, 0, sB>>>(W2, p_Wt);
    cudaEventRecord(evB, sB);

    cudaStreamWaitEvent(0, evA, 0);

    // ---- layer 1: gather half0; colstats(half0) overlaps gather half1
    k_gather1<<<HALF_R / 2, 256>>>(x, p_E, p_y, 0, HALF_R);
    cudaEventRecord(evG1a, 0);
    cudaStreamWaitEvent(sC, evG1a, 0);
    k_colstats<<<(HALF_R + CS_ROWS - 1) / CS_ROWS, 512, 0, sC>>>(p_y, p_stats, 0, HALF_R);
    cudaEventRecord(evCS, sC);
    k_gather1<<<(N_NODES - HALF_R + 1) / 2, 256>>>(x, p_E, p_y, HALF_R, N_NODES);
    k_colstats<<<(N_NODES - HALF_R + CS_ROWS - 1) / CS_ROWS, 512>>>(p_y, p_stats,
                                                                    HALF_R, N_NODES);
    cudaStreamWaitEvent(0, evCS, 0);
    k_finalize<<<1, HIDDEN>>>(p_stats, g1, be1, p_coefA, p_coefB);

    // ---- layer 2: full gather, then full GEMM (sequential — no contention)
    k_gather2<<<(N_NODES + 1) / 2, 256>>>(p_y, p_coefA, p_coefB, p_A);
    cudaStreamWaitEvent(0, evB, 0);
    {
        dim3 grid(HIDDEN / 128, ROWSP / 128);
        k_mma_gemm<<<grid, GT, G_SMEM>>>(p_A, p_Wt, p_y, p_stats + 2 * HIDDEN, HIDDEN);
    }
    k_finalize<<<1, HIDDEN>>>(p_stats + 2 * HIDDEN, g2, be2,
                              p_coefA + HIDDEN, p_coefB + HIDDEN);

    // ---- pooling (fused layer-2 BN+ReLU) + head
    k_pool_bn<<<(N_NODES + 255) / 256, 512>>>(p_y, batch, p_coefA + HIDDEN, p_coefB + HIDDEN);
    k_lin1<<<N_GRAPHS, HALF_H>>>(Wl1, bl1);
    k_lin2<<<N_GRAPHS, OUT_DIM>>>(Wl2, bl2, out);
}